// round 2
// baseline (speedup 1.0000x reference)
#include <cuda_runtime.h>

// VectorQuantizer: x [B=32, C=64, H=64, W=64] fp32, emb [K=512, D=64] fp32.
// For each pixel n (B*H*W = 131072): argmin_k (x_sq[n] + e_sq[k] - 2 * x[n].e[k]),
// then out[b, :, h, w] = emb[argmin].
//
// Compute bound: N*K*D = 4.295G FMA fp32. GEMM-style blocking:
//   block = 256 threads, 64 pixels x 512 codes; k-tiles of 64 codes;
//   per thread: 4 pixels x 4 codes accumulator tile, LDS.128 operand feeds.

#define KCODES 512
#define DDIM   64
#define PT     64   // pixels per block
#define KT     64   // codes per k-tile
#define NTHR   256
#define NKT    (KCODES / KT)   // 8
#define PAD    4

__global__ __launch_bounds__(NTHR, 2)
void vq_kernel(const float* __restrict__ x,
               const float* __restrict__ emb,
               float* __restrict__ out,
               int HW, int CHW)
{
    __shared__ float xs[DDIM][PT + PAD];   // xs[d][p]  (row stride 68 floats = 272B, 16B-aligned)
    __shared__ float es[DDIM][KT + PAD];   // es[d][k]
    __shared__ float xsq[PT];
    __shared__ float esq[KT];
    __shared__ float red_val[PT][16];
    __shared__ int   red_idx[PT][16];
    __shared__ int   widx[PT];

    const int t   = threadIdx.x;
    const int n0  = blockIdx.x * PT;      // first pixel of this block
    const int b   = n0 >> 12;             // / 4096 (HW); tiles never cross batch (4096 % 64 == 0)
    const int hw0 = n0 & 4095;

    // ---- stage x tile: xs[c][p] = x[b, c, hw0+p] ----
    const float* xb = x + (size_t)b * CHW + hw0;
    #pragma unroll
    for (int it = 0; it < (DDIM * PT) / NTHR; ++it) {   // 16 iters
        int lin = it * NTHR + t;
        int c = lin >> 6;
        int p = lin & 63;
        xs[c][p] = xb[c * HW + p];
    }
    __syncthreads();

    // ---- per-pixel ||x||^2, ascending d, product rounded then added (matches jnp.sum(x*x)) ----
    if (t < PT) {
        float s = 0.0f;
        #pragma unroll 8
        for (int d = 0; d < DDIM; ++d) {
            float v = xs[d][t];
            s = __fadd_rn(s, __fmul_rn(v, v));
        }
        xsq[t] = s;
    }
    __syncthreads();

    // thread tile mapping: 16 pixel-groups x 16 code-groups
    const int px = (t & 15) * 4;    // 4 consecutive pixels
    const int kg = (t >> 4) * 4;    // 4 consecutive codes within k-tile

    float xsq_r[4];
    #pragma unroll
    for (int i = 0; i < 4; ++i) xsq_r[i] = xsq[px + i];

    float best[4];
    int   bidx[4];
    #pragma unroll
    for (int i = 0; i < 4; ++i) { best[i] = 3.4e38f; bidx[i] = 0; }

    for (int kt = 0; kt < NKT; ++kt) {
        __syncthreads();   // protect es/esq reuse from previous tile
        // ---- stage e tile transposed: es[d][k] = emb[kt*KT + k][d] ----
        #pragma unroll
        for (int it = 0; it < (KT * DDIM / 4) / NTHR; ++it) {  // 4 iters of float4
            int lin = it * NTHR + t;        // 0..1023
            int k   = lin >> 4;
            int d4  = (lin & 15) * 4;
            float4 ev = *(const float4*)(emb + (size_t)(kt * KT + k) * DDIM + d4);
            es[d4 + 0][k] = ev.x;
            es[d4 + 1][k] = ev.y;
            es[d4 + 2][k] = ev.z;
            es[d4 + 3][k] = ev.w;
        }
        __syncthreads();
        // ---- per-code ||e||^2 (ascending d, rounded product then add) ----
        if (t < KT) {
            float s = 0.0f;
            #pragma unroll 8
            for (int d = 0; d < DDIM; ++d) {
                float v = es[d][t];
                s = __fadd_rn(s, __fmul_rn(v, v));
            }
            esq[t] = s;
        }
        __syncthreads();

        // ---- 4x4 dot-product accumulation over d ----
        float acc00 = 0.f, acc01 = 0.f, acc02 = 0.f, acc03 = 0.f;
        float acc10 = 0.f, acc11 = 0.f, acc12 = 0.f, acc13 = 0.f;
        float acc20 = 0.f, acc21 = 0.f, acc22 = 0.f, acc23 = 0.f;
        float acc30 = 0.f, acc31 = 0.f, acc32 = 0.f, acc33 = 0.f;

        #pragma unroll 16
        for (int d = 0; d < DDIM; ++d) {
            float4 xv = *(const float4*)&xs[d][px];
            float4 ev = *(const float4*)&es[d][kg];
            acc00 = fmaf(xv.x, ev.x, acc00);
            acc01 = fmaf(xv.x, ev.y, acc01);
            acc02 = fmaf(xv.x, ev.z, acc02);
            acc03 = fmaf(xv.x, ev.w, acc03);
            acc10 = fmaf(xv.y, ev.x, acc10);
            acc11 = fmaf(xv.y, ev.y, acc11);
            acc12 = fmaf(xv.y, ev.z, acc12);
            acc13 = fmaf(xv.y, ev.w, acc13);
            acc20 = fmaf(xv.z, ev.x, acc20);
            acc21 = fmaf(xv.z, ev.y, acc21);
            acc22 = fmaf(xv.z, ev.z, acc22);
            acc23 = fmaf(xv.z, ev.w, acc23);
            acc30 = fmaf(xv.w, ev.x, acc30);
            acc31 = fmaf(xv.w, ev.y, acc31);
            acc32 = fmaf(xv.w, ev.z, acc32);
            acc33 = fmaf(xv.w, ev.w, acc33);
        }

        // ---- fold into running argmin: score = fl(fl(xsq + esq) - 2*dot) ----
        float accm[4][4] = {{acc00,acc01,acc02,acc03},
                            {acc10,acc11,acc12,acc13},
                            {acc20,acc21,acc22,acc23},
                            {acc30,acc31,acc32,acc33}};
        #pragma unroll
        for (int j = 0; j < 4; ++j) {
            int   k  = kt * KT + kg + j;
            float eq = esq[kg + j];
            #pragma unroll
            for (int i = 0; i < 4; ++i) {
                float t1 = __fadd_rn(xsq_r[i], eq);
                float sc = __fsub_rn(t1, __fmul_rn(2.0f, accm[i][j]));
                if (sc < best[i]) { best[i] = sc; bidx[i] = k; }   // k ascending -> lowest idx kept
            }
        }
    }

    // ---- cross-thread argmin reduction (16 code-groups per pixel) ----
    {
        int g = t >> 4;
        #pragma unroll
        for (int i = 0; i < 4; ++i) {
            red_val[px + i][g] = best[i];
            red_idx[px + i][g] = bidx[i];
        }
    }
    __syncthreads();
    if (t < PT) {
        float bv = red_val[t][0];
        int   bi = red_idx[t][0];
        #pragma unroll
        for (int g = 1; g < 16; ++g) {
            float v  = red_val[t][g];
            int   id = red_idx[t][g];
            if (v < bv || (v == bv && id < bi)) { bv = v; bi = id; }
        }
        widx[t] = bi;
    }
    __syncthreads();

    // ---- gather + write out[b, c, hw0+p] = emb[widx[p]][c] ----
    float* ob = out + (size_t)b * CHW + hw0;
    #pragma unroll
    for (int it = 0; it < (DDIM * PT) / NTHR; ++it) {
        int lin = it * NTHR + t;
        int c = lin >> 6;
        int p = lin & 63;
        ob[c * HW + p] = emb[(size_t)widx[p] * DDIM + c];
    }
}

extern "C" void kernel_launch(void* const* d_in, const int* in_sizes, int n_in,
                              void* d_out, int out_size)
{
    const float* x   = (const float*)d_in[0];   // [32, 64, 64, 64]
    const float* emb = (const float*)d_in[1];   // [512, 64]
    float* out = (float*)d_out;

    const int HW  = 64 * 64;          // 4096
    const int CHW = DDIM * HW;        // 262144
    const int N   = in_sizes[0] / DDIM;  // 131072 pixels

    dim3 grid(N / PT);                // 2048
    dim3 block(NTHR);
    vq_kernel<<<grid, block>>>(x, emb, out, HW, CHW);
}

// round 3
// speedup vs baseline: 1.1067x; 1.1067x over previous
#include <cuda_runtime.h>
#include <cstdint>

// VectorQuantizer: x [32,64,64,64] fp32, emb [512,64] fp32.
// argmin_k ( x_sq + e_sq[k] - 2 x.e[k] ) per pixel, gather emb[argmin] to [B,C,H,W].
//
// FFMA2 (fma.rn.f32x2) GEMM: 256 threads, block tile 128 px x 128 codes (4 k-tiles),
// per-thread 8 px x 8 codes = 32 packed accumulators. Code-dim packing with
// duplicated x keeps each lane's dot bitwise identical to the scalar sequential
// fmaf chain (round-2 kernel, rel_err 0.0) -> argmin provably unchanged.

#define KCODES 512
#define DDIM   64
#define PT     128   // pixels per block
#define KT     128   // codes per k-tile
#define NKT    (KCODES / KT)   // 4
#define NTHR   256

__global__ __launch_bounds__(NTHR, 2)
void vq_kernel(const float* __restrict__ x,
               const float* __restrict__ emb,
               float* __restrict__ out,
               int HW, int CHW)
{
    // [d][group] of float4; group g covers 8 lanes split A(0..3)/B(4..7).
    // Warp inner loads: x -> 16 unique consecutive 16B lines (2-phase, optimal),
    // e -> 2-address broadcast. No padding needed.
    __shared__ float4 xsA[DDIM][16];
    __shared__ float4 xsB[DDIM][16];
    __shared__ float4 esA[DDIM][16];
    __shared__ float4 esB[DDIM][16];
    __shared__ float  xsq[PT];
    __shared__ float  esq[KT];
    __shared__ float  red_val[PT][16];
    __shared__ int    red_idx[PT][16];
    __shared__ int    widx[PT];

    const int t   = threadIdx.x;
    const int n0  = blockIdx.x * PT;
    const int b   = n0 >> 12;          // HW = 4096; tiles never cross batch
    const int hw0 = n0 & 4095;

    // ---- stage x tile: element (c, p) -> xsA/xsB[c][p>>3] ----
    const float* xb = x + (size_t)b * CHW + hw0;
    #pragma unroll
    for (int it = 0; it < (DDIM * PT) / NTHR; ++it) {   // 32 iters, coalesced reads
        int lin = it * NTHR + t;
        int c = lin >> 7;
        int p = lin & 127;
        float v = xb[c * HW + p];
        int pg = p >> 3, sub = p & 7;
        float* dst = (sub < 4) ? (float*)&xsA[c][pg] : (float*)&xsB[c][pg];
        dst[sub & 3] = v;
    }
    __syncthreads();

    // ---- ||x||^2 per pixel: ascending d, rounded product then add (matches jnp.sum(x*x)) ----
    if (t < PT) {
        int pg = t >> 3, sub = t & 7;
        float s = 0.0f;
        #pragma unroll 8
        for (int d = 0; d < DDIM; ++d) {
            const float* src = (sub < 4) ? (const float*)&xsA[d][pg]
                                         : (const float*)&xsB[d][pg];
            float v = src[sub & 3];
            s = __fadd_rn(s, __fmul_rn(v, v));
        }
        xsq[t] = s;
    }
    __syncthreads();

    const int pxg = t & 15;   // pixel group: 8 consecutive pixels
    const int kgg = t >> 4;   // code group:  8 consecutive codes in tile

    float xsq_r[8];
    #pragma unroll
    for (int i = 0; i < 8; ++i) xsq_r[i] = xsq[pxg * 8 + i];

    float best[8];
    int   bidx[8];
    #pragma unroll
    for (int i = 0; i < 8; ++i) { best[i] = 3.4e38f; bidx[i] = 0; }

    for (int kt = 0; kt < NKT; ++kt) {
        __syncthreads();   // protect es/esq reuse from previous tile
        // ---- stage e tile: emb[kt*KT + k][d] -> esA/esB[d][k>>3] ----
        #pragma unroll
        for (int it = 0; it < (KT * DDIM / 4) / NTHR; ++it) {  // 8 iters of float4
            int lin = it * NTHR + t;         // 0..2047
            int k   = lin >> 4;
            int d4  = (lin & 15) * 4;
            float4 ev = *(const float4*)(emb + (size_t)(kt * KT + k) * DDIM + d4);
            int kg = k >> 3, sub = k & 7;
            float vv[4] = {ev.x, ev.y, ev.z, ev.w};
            #pragma unroll
            for (int j = 0; j < 4; ++j) {
                float* dst = (sub < 4) ? (float*)&esA[d4 + j][kg]
                                       : (float*)&esB[d4 + j][kg];
                dst[sub & 3] = vv[j];
            }
        }
        __syncthreads();
        // ---- ||e||^2 per code (ascending d, rounded product then add) ----
        if (t < KT) {
            int kg = t >> 3, sub = t & 7;
            float s = 0.0f;
            #pragma unroll 8
            for (int d = 0; d < DDIM; ++d) {
                const float* src = (sub < 4) ? (const float*)&esA[d][kg]
                                             : (const float*)&esB[d][kg];
                float v = src[sub & 3];
                s = __fadd_rn(s, __fmul_rn(v, v));
            }
            esq[t] = s;
        }
        __syncthreads();

        // ---- 8 px x 8 codes packed-FFMA2 accumulation over d ----
        // acc[i][jp] packs codes (jp*2, jp*2+1); lane order = ascending k.
        uint64_t acc[8][4];
        #pragma unroll
        for (int i = 0; i < 8; ++i)
            #pragma unroll
            for (int jp = 0; jp < 4; ++jp) acc[i][jp] = 0ull;  // {0.f, 0.f}

        #pragma unroll 8
        for (int d = 0; d < DDIM; ++d) {
            float4 xq0 = xsA[d][pxg];
            float4 xq1 = xsB[d][pxg];
            const uint64_t* eA = (const uint64_t*)&esA[d][kgg];
            const uint64_t* eB = (const uint64_t*)&esB[d][kgg];
            uint64_t e0 = eA[0], e1 = eA[1], e2 = eB[0], e3 = eB[1];
            float xv[8] = {xq0.x, xq0.y, xq0.z, xq0.w,
                           xq1.x, xq1.y, xq1.z, xq1.w};
            #pragma unroll
            for (int i = 0; i < 8; ++i) {
                uint64_t xd;
                asm("mov.b64 %0, {%1, %1};" : "=l"(xd) : "f"(xv[i]));
                asm("fma.rn.f32x2 %0, %1, %2, %0;" : "+l"(acc[i][0]) : "l"(xd), "l"(e0));
                asm("fma.rn.f32x2 %0, %1, %2, %0;" : "+l"(acc[i][1]) : "l"(xd), "l"(e1));
                asm("fma.rn.f32x2 %0, %1, %2, %0;" : "+l"(acc[i][2]) : "l"(xd), "l"(e2));
                asm("fma.rn.f32x2 %0, %1, %2, %0;" : "+l"(acc[i][3]) : "l"(xd), "l"(e3));
            }
        }

        // ---- fold into running argmin: score = fl(fl(xsq+esq) - 2*dot), ascending k ----
        #pragma unroll
        for (int jp = 0; jp < 4; ++jp) {
            int   kloc = kgg * 8 + jp * 2;
            int   k0   = kt * KT + kloc;
            float eq0  = esq[kloc];
            float eq1  = esq[kloc + 1];
            #pragma unroll
            for (int i = 0; i < 8; ++i) {
                float lo, hi;
                asm("mov.b64 {%0, %1}, %2;" : "=f"(lo), "=f"(hi) : "l"(acc[i][jp]));
                float s0 = __fsub_rn(__fadd_rn(xsq_r[i], eq0), __fmul_rn(2.0f, lo));
                float s1 = __fsub_rn(__fadd_rn(xsq_r[i], eq1), __fmul_rn(2.0f, hi));
                if (s0 < best[i]) { best[i] = s0; bidx[i] = k0; }
                if (s1 < best[i]) { best[i] = s1; bidx[i] = k0 + 1; }
            }
        }
    }

    // ---- cross-thread argmin reduction (16 code-groups per pixel) ----
    #pragma unroll
    for (int i = 0; i < 8; ++i) {
        red_val[pxg * 8 + i][kgg] = best[i];
        red_idx[pxg * 8 + i][kgg] = bidx[i];
    }
    __syncthreads();
    if (t < PT) {
        float bv = red_val[t][0];
        int   bi = red_idx[t][0];
        #pragma unroll
        for (int g = 1; g < 16; ++g) {
            float v  = red_val[t][g];
            int   id = red_idx[t][g];
            if (v < bv || (v == bv && id < bi)) { bv = v; bi = id; }
        }
        widx[t] = bi;
    }
    __syncthreads();

    // ---- gather + write out[b, c, hw0+p] = emb[widx[p]][c] ----
    float* ob = out + (size_t)b * CHW + hw0;
    #pragma unroll
    for (int it = 0; it < (DDIM * PT) / NTHR; ++it) {
        int lin = it * NTHR + t;
        int c = lin >> 7;
        int p = lin & 127;
        ob[c * HW + p] = emb[(size_t)widx[p] * DDIM + c];
    }
}

extern "C" void kernel_launch(void* const* d_in, const int* in_sizes, int n_in,
                              void* d_out, int out_size)
{
    const float* x   = (const float*)d_in[0];   // [32, 64, 64, 64]
    const float* emb = (const float*)d_in[1];   // [512, 64]
    float* out = (float*)d_out;

    const int HW  = 64 * 64;             // 4096
    const int CHW = DDIM * HW;           // 262144
    const int N   = in_sizes[0] / DDIM;  // 131072 pixels

    dim3 grid(N / PT);                   // 1024
    dim3 block(NTHR);
    vq_kernel<<<grid, block>>>(x, emb, out, HW, CHW);
}